// round 3
// baseline (speedup 1.0000x reference)
#include <cuda_runtime.h>
#include <math.h>

// Problem constants
#define NB   64     // batch
#define NL   32     // caption length
#define NT   31     // decode steps = L-1
#define NV   16000  // vocab
#define NE   512    // ENC = DEC = ATT
#define NEMB 256
#define NP   256    // pixels

#define GRIDN 128   // persistent kernel blocks (must all be co-resident)

// ---------------- device scratch (no allocation allowed) ----------------
__device__ float g_enc [NB * NP * NE];        // [B][P][C]
__device__ float g_att1[NB * NP * NE];        // [B][P][A]
__device__ float g_mean[NB * NE];
__device__ float g_h   [NB * NE];
__device__ float g_c   [NB * NE];
__device__ float g_Hall[NT * NB * NE];        // h2 per step
__device__ float g_xprj[NT * NB * 2048];      // emb part of gates + b_ih + b_hh
__device__ float g_ybuf[8 * NB * 1024];       // partials of h @ [Wdec; Wbeta]
__device__ float g_gbuf[4 * NB * 2048];       // partials of [h|awe] @ Wg
__device__ float g_awe [NB * NE];
__device__ float g_Wcat[1024 * 512];          // stacked [Wdec; Wbeta]
__device__ float g_Wg  [2048 * 1024];         // [Whh | W_ih[:,256:768]] per gate row
__device__ float g_bsum[2048];                // b_ih + b_hh
__device__ int   g_capx[2048];                // emb row per (t,b)
__device__ int   g_rowA[2048];                // active row -> t*64+b (into Hall)
__device__ int   g_rowO[2048];                // active row -> b*31+t (into out)
__device__ int   g_nact[1];
__device__ unsigned g_bar[2];                 // [0]=count, [1]=release phase

__device__ __forceinline__ float sigf(float x) { return 1.0f / (1.0f + expf(-x)); }

// ============================================================================
// High-throughput SGEMM: C[M,N] = A[M,K] * B[N,K]^T (+bias)
// 128x128 tile, BK=8, 256 threads, double-buffered. Gather/scatter rows.
// ============================================================================
__global__ void __launch_bounds__(256, 2)
sgemm128(const float* __restrict__ A, int lda, const int* __restrict__ arow,
         const float* __restrict__ B, int ldb,
         const float* __restrict__ bias,
         float* __restrict__ C, int ldc, const int* __restrict__ crow,
         int M, const int* __restrict__ Mdev, int K)
{
    int Mv = Mdev ? *Mdev : M;
    int m0 = blockIdx.x * 128;
    if (m0 >= Mv) return;
    int n0 = blockIdx.y * 128;

    __shared__ float As[2][8][128];
    __shared__ float Bs[2][8][128];

    int tid = threadIdx.x;
    int lrow = tid >> 1;
    int lk4  = (tid & 1) * 4;

    int rowm = m0 + lrow;
    int ca   = (rowm < Mv) ? rowm : (Mv - 1);
    int ar   = arow ? arow[ca] : ca;
    const float* Ap = A + (long long)ar * lda + lk4;
    const float* Bp = B + (long long)(n0 + lrow) * ldb + lk4;

    int tx = tid & 15;
    int ty = tid >> 4;

    float acc[8][8];
#pragma unroll
    for (int i = 0; i < 8; i++)
#pragma unroll
        for (int j = 0; j < 8; j++) acc[i][j] = 0.0f;

    {
        float4 a4 = *(const float4*)Ap;
        float4 b4 = *(const float4*)Bp;
        As[0][lk4 + 0][lrow] = a4.x; As[0][lk4 + 1][lrow] = a4.y;
        As[0][lk4 + 2][lrow] = a4.z; As[0][lk4 + 3][lrow] = a4.w;
        Bs[0][lk4 + 0][lrow] = b4.x; Bs[0][lk4 + 1][lrow] = b4.y;
        Bs[0][lk4 + 2][lrow] = b4.z; Bs[0][lk4 + 3][lrow] = b4.w;
    }
    __syncthreads();

    int ntiles = K >> 3;
    int buf = 0;
    for (int t = 0; t < ntiles; t++) {
        float4 na, nb;
        bool more = (t + 1 < ntiles);
        if (more) {
            int kk = (t + 1) << 3;
            na = *(const float4*)(Ap + kk);
            nb = *(const float4*)(Bp + kk);
        }
#pragma unroll
        for (int k = 0; k < 8; k++) {
            float a[8], b[8];
            *(float4*)(a)     = *(const float4*)&As[buf][k][ty * 4];
            *(float4*)(a + 4) = *(const float4*)&As[buf][k][64 + ty * 4];
            *(float4*)(b)     = *(const float4*)&Bs[buf][k][tx * 4];
            *(float4*)(b + 4) = *(const float4*)&Bs[buf][k][64 + tx * 4];
#pragma unroll
            for (int i = 0; i < 8; i++)
#pragma unroll
                for (int j = 0; j < 8; j++)
                    acc[i][j] = fmaf(a[i], b[j], acc[i][j]);
        }
        if (more) {
            int nbuf = buf ^ 1;
            As[nbuf][lk4 + 0][lrow] = na.x; As[nbuf][lk4 + 1][lrow] = na.y;
            As[nbuf][lk4 + 2][lrow] = na.z; As[nbuf][lk4 + 3][lrow] = na.w;
            Bs[nbuf][lk4 + 0][lrow] = nb.x; Bs[nbuf][lk4 + 1][lrow] = nb.y;
            Bs[nbuf][lk4 + 2][lrow] = nb.z; Bs[nbuf][lk4 + 3][lrow] = nb.w;
            __syncthreads();
            buf = nbuf;
        }
    }

    float bv[8];
#pragma unroll
    for (int jh = 0; jh < 2; jh++)
#pragma unroll
        for (int j = 0; j < 4; j++)
            bv[jh * 4 + j] = bias ? bias[n0 + jh * 64 + tx * 4 + j] : 0.0f;

#pragma unroll
    for (int i = 0; i < 8; i++) {
        int r = m0 + ((i < 4) ? (ty * 4 + i) : (64 + ty * 4 + i - 4));
        if (r >= Mv) continue;
        int cr = crow ? crow[r] : r;
        float* Cp = C + (long long)cr * ldc + n0;
#pragma unroll
        for (int jh = 0; jh < 2; jh++) {
            float4 v;
            v.x = acc[i][jh * 4 + 0] + bv[jh * 4 + 0];
            v.y = acc[i][jh * 4 + 1] + bv[jh * 4 + 1];
            v.z = acc[i][jh * 4 + 2] + bv[jh * 4 + 2];
            v.w = acc[i][jh * 4 + 3] + bv[jh * 4 + 3];
            *(float4*)(Cp + jh * 64 + tx * 4) = v;
        }
    }
}

// ---------------- small tiled SGEMM (h0/c0 only) ----------------------------
__global__ void sgemm64(const float* __restrict__ A, int lda,
                        const float* __restrict__ B, int ldb,
                        const float* __restrict__ bias,
                        float* __restrict__ C, int ldc, int K)
{
    int n0 = blockIdx.y * 64;

    __shared__ float As[16][68];
    __shared__ float Bs[16][68];

    int tid = threadIdx.x;
    int tx = tid & 15, ty = tid >> 4;
    int lm = tid >> 2, lk = (tid & 3) * 4;

    const float* Arow = A + (long long)lm * lda;
    const float* Brow = B + (long long)(n0 + lm) * ldb;

    float acc[4][4];
#pragma unroll
    for (int i = 0; i < 4; i++)
#pragma unroll
        for (int j = 0; j < 4; j++) acc[i][j] = 0.0f;

    for (int kk = 0; kk < K; kk += 16) {
        float4 av = *(const float4*)(Arow + kk + lk);
        float4 bv = *(const float4*)(Brow + kk + lk);
        __syncthreads();
        As[lk + 0][lm] = av.x; As[lk + 1][lm] = av.y;
        As[lk + 2][lm] = av.z; As[lk + 3][lm] = av.w;
        Bs[lk + 0][lm] = bv.x; Bs[lk + 1][lm] = bv.y;
        Bs[lk + 2][lm] = bv.z; Bs[lk + 3][lm] = bv.w;
        __syncthreads();
#pragma unroll
        for (int k = 0; k < 16; k++) {
            float4 a4 = *(const float4*)&As[k][ty * 4];
            float4 b4 = *(const float4*)&Bs[k][tx * 4];
            float aa[4] = {a4.x, a4.y, a4.z, a4.w};
            float bb[4] = {b4.x, b4.y, b4.z, b4.w};
#pragma unroll
            for (int i = 0; i < 4; i++)
#pragma unroll
                for (int j = 0; j < 4; j++) acc[i][j] = fmaf(aa[i], bb[j], acc[i][j]);
        }
    }

#pragma unroll
    for (int i = 0; i < 4; i++) {
        float* Cp = C + (long long)(ty * 4 + i) * ldc + n0 + tx * 4;
#pragma unroll
        for (int j = 0; j < 4; j++)
            Cp[j] = acc[i][j] + bias[n0 + tx * 4 + j];
    }
}

// ---------------- transpose encoder_out [B][C][P] -> enc [B][P][C] ----------
__global__ void transpose_enc(const float* __restrict__ eo, float* __restrict__ enc)
{
    __shared__ float t[32][33];
    int b = blockIdx.z;
    int c0 = blockIdx.x * 32, p0 = blockIdx.y * 32;
    int x = threadIdx.x, y = threadIdx.y;
    for (int i = y; i < 32; i += 8)
        t[i][x] = eo[((long long)b * NE + c0 + i) * NP + p0 + x];
    __syncthreads();
    for (int i = y; i < 32; i += 8)
        enc[((long long)b * NP + p0 + i) * NE + c0 + x] = t[x][i];
}

// ---------------- mean over pixels ------------------------------------------
__global__ void mean_kernel(const float* __restrict__ eo, float* __restrict__ mean)
{
    int row = blockIdx.x * 8 + threadIdx.y;
    int lane = threadIdx.x;
    const float* src = eo + (long long)row * NP;
    float s = 0.0f;
    for (int p = lane; p < NP; p += 32) s += src[p];
#pragma unroll
    for (int o = 16; o > 0; o >>= 1) s += __shfl_xor_sync(0xffffffffu, s, o);
    if (lane == 0) mean[row] = s * (1.0f / NP);
}

// ---------------- setup: bias sum, emb indices, active-row compaction -------
__global__ void setup_kernel(const int* __restrict__ caps, const int* __restrict__ lens,
                             const float* __restrict__ b_ih, const float* __restrict__ b_hh)
{
    int tid = threadIdx.x;
    for (int j = tid; j < 2048; j += 256) g_bsum[j] = b_ih[j] + b_hh[j];
    for (int i = tid; i < NT * NB; i += 256) {
        int t = i / NB, b = i % NB;
        g_capx[i] = caps[b * NL + t];
    }
    __syncthreads();
    if (tid == 0) {
        int cnt = 0;
        for (int t = 0; t < NT; t++)
            for (int b = 0; b < NB; b++)
                if (t < lens[b] - 1) { g_rowA[cnt] = t * NB + b; g_rowO[cnt] = b * NT + t; cnt++; }
        g_nact[0] = cnt;
        for (int i = cnt; i < 2048; i++) { g_rowA[i] = 0; g_rowO[i] = 0; }
    }
}

// ---------------- build stacked weights [Wdec;Wbeta], [Whh | Wih_awe] -------
__global__ void wcat_kernel(const float* __restrict__ Wd, const float* __restrict__ Wb,
                            const float* __restrict__ Whh, const float* __restrict__ Wih)
{
    int f4 = blockIdx.x * blockDim.x + threadIdx.x;
    if (f4 < 131072) {                       // g_Wcat: 1024 rows x 512
        int n = f4 >> 7, q = (f4 & 127) * 4;
        const float* src = (n < 512) ? (Wd + n * 512 + q) : (Wb + (n - 512) * 512 + q);
        *(float4*)(g_Wcat + f4 * 4) = *(const float4*)src;
    } else {
        int r = f4 - 131072;                 // g_Wg: 2048 rows x 1024
        if (r >= 524288) return;
        int n = r >> 8, q = (r & 255) * 4;
        const float* src = (q < 512) ? (Whh + n * 512 + q) : (Wih + n * 768 + 256 + (q - 512));
        *(float4*)(g_Wg + r * 4) = *(const float4*)src;
    }
}

// ============================================================================
// PERSISTENT RECURRENCE KERNEL (grid = GRIDN blocks x 256 threads)
// ============================================================================
__device__ __forceinline__ void gbar(unsigned target)
{
    __syncthreads();
    if (threadIdx.x == 0) {
        __threadfence();                              // release + L1 flush
        unsigned p = atomicAdd(&g_bar[0], 1u);
        if (p == target * GRIDN - 1u) {
            atomicExch(&g_bar[1], target);
        } else {
            while (atomicAdd(&g_bar[1], 0u) < target) { }
        }
        __threadfence();                              // acquire + L1 flush
    }
    __syncthreads();
}

// 64xN-tile x kchunk partial GEMM: C[0..63][n0..n0+63] += A[64xK] * B[NxK]^T
__device__ __forceinline__ void tile64(const float* __restrict__ A, int lda,
                                       const float* __restrict__ B, int ldb,
                                       float* __restrict__ C, int ldc,
                                       int n0, int kchunk, float* sh)
{
    float (*As)[68] = (float(*)[68])sh;
    float (*Bs)[68] = (float(*)[68])(sh + 16 * 68);
    int tid = threadIdx.x;
    int tx = tid & 15, ty = tid >> 4;
    int lm = tid >> 2, lk = (tid & 3) * 4;

    const float* Arow = A + (long long)lm * lda;
    const float* Brow = B + (long long)(n0 + lm) * ldb;

    float acc[4][4];
#pragma unroll
    for (int i = 0; i < 4; i++)
#pragma unroll
        for (int j = 0; j < 4; j++) acc[i][j] = 0.0f;

    for (int kk = 0; kk < kchunk; kk += 16) {
        float4 av = *(const float4*)(Arow + kk + lk);
        float4 bv = *(const float4*)(Brow + kk + lk);
        __syncthreads();
        As[lk + 0][lm] = av.x; As[lk + 1][lm] = av.y;
        As[lk + 2][lm] = av.z; As[lk + 3][lm] = av.w;
        Bs[lk + 0][lm] = bv.x; Bs[lk + 1][lm] = bv.y;
        Bs[lk + 2][lm] = bv.z; Bs[lk + 3][lm] = bv.w;
        __syncthreads();
#pragma unroll
        for (int k = 0; k < 16; k++) {
            float4 a4 = *(const float4*)&As[k][ty * 4];
            float4 b4 = *(const float4*)&Bs[k][tx * 4];
            float aa[4] = {a4.x, a4.y, a4.z, a4.w};
            float bb[4] = {b4.x, b4.y, b4.z, b4.w};
#pragma unroll
            for (int i = 0; i < 4; i++)
#pragma unroll
                for (int j = 0; j < 4; j++) acc[i][j] = fmaf(aa[i], bb[j], acc[i][j]);
        }
    }
    __syncthreads();
#pragma unroll
    for (int i = 0; i < 4; i++) {
        float* Cp = C + (long long)(ty * 4 + i) * ldc + n0 + tx * 4;
#pragma unroll
        for (int j = 0; j < 4; j++) Cp[j] = acc[i][j];
    }
}

__global__ void __launch_bounds__(256, 1)
recurrence_kernel(const float* __restrict__ eo,
                  const float* __restrict__ b_dec_att,
                  const float* __restrict__ w_full,
                  const float* __restrict__ b_full,
                  const float* __restrict__ b_beta)
{
    __shared__ float sh[2304];
    int blk = blockIdx.x;
    int tid = threadIdx.x;

    for (int t = 0; t < NT; t++) {
        unsigned base = (unsigned)(t * 4);

        // ---- Phase A: y = h @ [Wdec; Wbeta]^T  (16 n-tiles x 8 k-splits)
        {
            int kz = blk >> 4;             // 0..7, kchunk 64
            int nt = blk & 15;             // 0..15
            tile64(g_h + kz * 64, 512,
                   g_Wcat + kz * 64, 512,
                   g_ybuf + kz * (NB * 1024), 1024,
                   nt * 64, 64, sh);
        }
        gbar(base + 1);

        // ---- Phase B: attention per batch (blocks 0..63)
        if (blk < NB) {
            int b = blk;
            float* att2_s = sh;            // 512
            float* w_s    = sh + 512;      // 512
            float* red_s  = sh + 1024;     // 256
            float* alpha_s= sh + 1280;     // 256

            for (int a = tid; a < 512; a += 256) {
                float v = b_dec_att[a];
#pragma unroll
                for (int kz = 0; kz < 8; kz++) v += g_ybuf[kz * (NB * 1024) + b * 1024 + a];
                att2_s[a] = v;
                w_s[a] = w_full[a];
            }
            __syncthreads();

            const float* arow = g_att1 + ((long long)b * NP + tid) * NE;
            float acc = 0.0f;
#pragma unroll 4
            for (int a = 0; a < 512; a += 4) {
                float4 v4 = *(const float4*)(arow + a);
                acc = fmaf(fmaxf(v4.x + att2_s[a + 0], 0.0f), w_s[a + 0], acc);
                acc = fmaf(fmaxf(v4.y + att2_s[a + 1], 0.0f), w_s[a + 1], acc);
                acc = fmaf(fmaxf(v4.z + att2_s[a + 2], 0.0f), w_s[a + 2], acc);
                acc = fmaf(fmaxf(v4.w + att2_s[a + 3], 0.0f), w_s[a + 3], acc);
            }
            acc += b_full[0];

            red_s[tid] = acc; __syncthreads();
            for (int s = 128; s > 0; s >>= 1) {
                if (tid < s) red_s[tid] = fmaxf(red_s[tid], red_s[tid + s]);
                __syncthreads();
            }
            float mx = red_s[0]; __syncthreads();
            float ex = expf(acc - mx);
            red_s[tid] = ex; __syncthreads();
            for (int s = 128; s > 0; s >>= 1) {
                if (tid < s) red_s[tid] += red_s[tid + s];
                __syncthreads();
            }
            alpha_s[tid] = ex / red_s[0];
            __syncthreads();

            for (int c = tid; c < 512; c += 256) {
                const float* erow = eo + ((long long)b * NE + c) * NP;
                float s = 0.0f;
#pragma unroll 4
                for (int p = 0; p < NP; p += 4) {
                    float4 e4 = *(const float4*)(erow + p);
                    s = fmaf(e4.x, alpha_s[p + 0], s);
                    s = fmaf(e4.y, alpha_s[p + 1], s);
                    s = fmaf(e4.z, alpha_s[p + 2], s);
                    s = fmaf(e4.w, alpha_s[p + 3], s);
                }
                float gpre = b_beta[c];
#pragma unroll
                for (int kz = 0; kz < 8; kz++) gpre += g_ybuf[kz * (NB * 1024) + b * 1024 + 512 + c];
                g_awe[b * NE + c] = sigf(gpre) * s;
            }
        }
        gbar(base + 2);

        // ---- Phase C: gates partials = [h|awe] @ Wg^T  (32 n-tiles x 4 k-splits)
        {
            int kz = blk >> 5;             // 0..3, kchunk 256
            int nt = blk & 31;             // 0..31
            const float* Abase = (kz < 2) ? (g_h + (kz & 1) * 256) : (g_awe + (kz & 1) * 256);
            tile64(Abase, 512,
                   g_Wg + kz * 256, 1024,
                   g_gbuf + kz * (NB * 2048), 2048,
                   nt * 64, 256, sh);
        }
        gbar(base + 3);

        // ---- Phase D: reduce partials + LSTM pointwise
        {
            int idx = blk * 256 + tid;     // 0..32767 = 64 batches x 512 dims
            int b = idx >> 9, d = idx & 511;
            const float* xp = g_xprj + ((long long)t * NB + b) * 2048;
            float gi = xp[d], gf = xp[512 + d], gg = xp[1024 + d], go = xp[1536 + d];
#pragma unroll
            for (int kz = 0; kz < 4; kz++) {
                const float* gb = g_gbuf + kz * (NB * 2048) + b * 2048;
                gi += gb[d]; gf += gb[512 + d]; gg += gb[1024 + d]; go += gb[1536 + d];
            }
            float cn = sigf(gf) * g_c[b * NE + d] + sigf(gi) * tanhf(gg);
            float hn = sigf(go) * tanhf(cn);
            g_c[b * NE + d] = cn;
            g_h[b * NE + d] = hn;
            g_Hall[((long long)t * NB + b) * NE + d] = hn;
        }
        gbar(base + 4);
    }
}

// ---------------- host launch -----------------------------------------------
extern "C" void kernel_launch(void* const* d_in, const int* in_sizes, int n_in,
                              void* d_out, int out_size)
{
    const float* eo        = (const float*)d_in[0];
    const int*   caps      = (const int*)  d_in[1];
    const int*   lens      = (const int*)  d_in[2];
    const float* W_enc_att = (const float*)d_in[3];
    const float* b_enc_att = (const float*)d_in[4];
    const float* W_dec_att = (const float*)d_in[5];
    const float* b_dec_att = (const float*)d_in[6];
    const float* w_full    = (const float*)d_in[7];
    const float* b_full    = (const float*)d_in[8];
    const float* emb       = (const float*)d_in[9];
    const float* W_ih      = (const float*)d_in[10];
    const float* W_hh      = (const float*)d_in[11];
    const float* b_ih      = (const float*)d_in[12];
    const float* b_hh      = (const float*)d_in[13];
    const float* W_init_h  = (const float*)d_in[14];
    const float* b_init_h  = (const float*)d_in[15];
    const float* W_init_c  = (const float*)d_in[16];
    const float* b_init_c  = (const float*)d_in[17];
    const float* W_beta    = (const float*)d_in[18];
    const float* b_beta    = (const float*)d_in[19];
    const float* W_fc      = (const float*)d_in[20];
    const float* b_fc      = (const float*)d_in[21];
    float* out = (float*)d_out;

    float *enc, *att1, *mean, *h, *c, *Hall, *xprj, *bsum;
    int *capx, *rowA, *rowO, *nact;
    unsigned* bar;
    cudaGetSymbolAddress((void**)&enc,  g_enc);
    cudaGetSymbolAddress((void**)&att1, g_att1);
    cudaGetSymbolAddress((void**)&mean, g_mean);
    cudaGetSymbolAddress((void**)&h,    g_h);
    cudaGetSymbolAddress((void**)&c,    g_c);
    cudaGetSymbolAddress((void**)&Hall, g_Hall);
    cudaGetSymbolAddress((void**)&xprj, g_xprj);
    cudaGetSymbolAddress((void**)&bsum, g_bsum);
    cudaGetSymbolAddress((void**)&capx, g_capx);
    cudaGetSymbolAddress((void**)&rowA, g_rowA);
    cudaGetSymbolAddress((void**)&rowO, g_rowO);
    cudaGetSymbolAddress((void**)&nact, g_nact);
    cudaGetSymbolAddress((void**)&bar,  g_bar);

    // zero output (masked rows must be exactly 0) + reset grid barrier
    cudaMemsetAsync(out, 0, (size_t)out_size * sizeof(float));
    cudaMemsetAsync(bar, 0, 2 * sizeof(unsigned));

    transpose_enc<<<dim3(16, 8, 64), dim3(32, 8)>>>(eo, enc);
    mean_kernel<<<4096, dim3(32, 8)>>>(eo, mean);
    setup_kernel<<<1, 256>>>(caps, lens, b_ih, b_hh);
    wcat_kernel<<<2560, 256>>>(W_dec_att, W_beta, W_hh, W_ih);

    // att1 = enc @ W_enc_att^T + b   (M=16384, N=512, K=512)
    sgemm128<<<dim3(128, 4), 256>>>(enc, 512, nullptr, W_enc_att, 512, b_enc_att,
                                    att1, 512, nullptr, NB * NP, nullptr, 512);
    // h0 / c0
    sgemm64<<<dim3(1, 8), 256>>>(mean, 512, W_init_h, 512, b_init_h, h, 512, 512);
    sgemm64<<<dim3(1, 8), 256>>>(mean, 512, W_init_c, 512, b_init_c, c, 512, 512);
    // x_proj = emb[cap] @ W_ih[:, :256]^T + (b_ih + b_hh)
    sgemm128<<<dim3(16, 16), 256>>>(emb, 256, capx, W_ih, 768, bsum,
                                    xprj, 2048, nullptr, NT * NB, nullptr, 256);

    // fused 31-step recurrence (persistent, grid-barrier synchronized)
    recurrence_kernel<<<GRIDN, 256>>>(eo, b_dec_att, w_full, b_full, b_beta);

    // Final FC over compacted active rows: out[b,t,:] = Hall[t,b,:] @ W_fc^T + b_fc
    sgemm128<<<dim3(16, 125), 256>>>(Hall, 512, rowA, W_fc, 512, b_fc,
                                     out, NV, rowO, NT * NB, nact, 512);
}